// round 9
// baseline (speedup 1.0000x reference)
#include <cuda_runtime.h>
#include <cuda_fp16.h>
#include <cuda_bf16.h>
#include <cstdint>

#define N_NODES 4096
#define EMB     512
#define N_HEADS 8
#define KSP     128
#define HD      64
#define K_TOT   1536          // 3 * EMB (bf16 split: [hi|lo|hi] x [hi|hi|lo])

// Projected Q and K, both fp16. Row = 1KB; head slice = 128B, line-aligned.
__device__ __half g_Qh[N_NODES * EMB];
__device__ __half g_Kh[N_NODES * EMB];

// bf16-split operands for the projection GEMMs
__device__ __align__(16) __nv_bfloat16 g_X2 [N_NODES * K_TOT];   // [hi | lo | hi]
__device__ __align__(16) __nv_bfloat16 g_W2q[EMB * K_TOT];       // [hi | hi | lo]
__device__ __align__(16) __nv_bfloat16 g_W2k[EMB * K_TOT];

// Selection bitmap: 4096 bits per (h, n) row = 128 u32 words. 16MB total.
__device__ __align__(16) uint32_t g_bm[N_HEADS * N_NODES * 128];

// ════════════════ portable PTX helpers (valid at compute_103) ═══════════════
__device__ __forceinline__ uint32_t smem_u32_of(const void* p) {
    uint32_t a;
    asm("{ .reg .u64 t; cvta.to.shared.u64 t, %1; cvt.u32.u64 %0, t; }" : "=r"(a) : "l"(p));
    return a;
}
__device__ __forceinline__ void ldsm_x4(uint32_t* r, uint32_t addr) {
    asm volatile("ldmatrix.sync.aligned.m8n8.x4.shared.b16 {%0,%1,%2,%3}, [%4];"
                 : "=r"(r[0]), "=r"(r[1]), "=r"(r[2]), "=r"(r[3]) : "r"(addr));
}
__device__ __forceinline__ void mma_bf16(float* c, const uint32_t* a, const uint32_t* b) {
    asm volatile(
        "mma.sync.aligned.m16n8k16.row.col.f32.bf16.bf16.f32 "
        "{%0,%1,%2,%3}, {%4,%5,%6,%7}, {%8,%9}, {%0,%1,%2,%3};"
        : "+f"(c[0]), "+f"(c[1]), "+f"(c[2]), "+f"(c[3])
        : "r"(a[0]), "r"(a[1]), "r"(a[2]), "r"(a[3]), "r"(b[0]), "r"(b[1]));
}
__device__ __forceinline__ void mma_f16(float* c, const uint32_t* a, const uint32_t* b) {
    asm volatile(
        "mma.sync.aligned.m16n8k16.row.col.f32.f16.f16.f32 "
        "{%0,%1,%2,%3}, {%4,%5,%6,%7}, {%8,%9}, {%0,%1,%2,%3};"
        : "+f"(c[0]), "+f"(c[1]), "+f"(c[2]), "+f"(c[3])
        : "r"(a[0]), "r"(a[1]), "r"(a[2]), "r"(a[3]), "r"(b[0]), "r"(b[1]));
}
__device__ __forceinline__ void cp16(uint32_t saddr, const void* gaddr) {
    asm volatile("cp.async.cg.shared.global [%0], [%1], 16;" :: "r"(saddr), "l"(gaddr));
}
#define CP_COMMIT() asm volatile("cp.async.commit_group;" ::: "memory")
#define CP_WAIT0()  asm volatile("cp.async.wait_group 0;" ::: "memory")
#define CP_WAIT1()  asm volatile("cp.async.wait_group 1;" ::: "memory")

// ---------------------------------------------------------------------------
// Fused: bf16 split conversion (blocks 0..5119) + bitmap zeroing (blocks 5120+).
// ---------------------------------------------------------------------------
#define CONV_BLKS (N_NODES + 2 * EMB)     // 5120
#define BMZ_BLKS  4096                    // 4M words / (256 thr * uint4)

__global__ void __launch_bounds__(256)
split_convert_all(const float* __restrict__ X,
                  const float* __restrict__ Wq, const float* __restrict__ Wk)
{
    const int r = blockIdx.x;
    if (r >= CONV_BLKS) {                 // bitmap zero blocks
        const int idx = (r - CONV_BLKS) * 256 + threadIdx.x;
        ((uint4*)g_bm)[idx] = make_uint4(0, 0, 0, 0);
        return;
    }
    const float* src;
    __nv_bfloat16* dst;
    int mode;
    if (r < N_NODES)            { src = X  + (size_t)r * EMB;              dst = g_X2  + (size_t)r * K_TOT;              mode = 0; }
    else if (r < N_NODES + EMB) { src = Wq + (size_t)(r - N_NODES) * EMB;  dst = g_W2q + (size_t)(r - N_NODES) * K_TOT;  mode = 1; }
    else                        { src = Wk + (size_t)(r - N_NODES - EMB) * EMB; dst = g_W2k + (size_t)(r - N_NODES - EMB) * K_TOT; mode = 1; }

    const int c = threadIdx.x * 2;
    float2 v = *(const float2*)(src + c);
    __nv_bfloat16 h0 = __float2bfloat16_rn(v.x);
    __nv_bfloat16 h1 = __float2bfloat16_rn(v.y);
    __nv_bfloat16 l0 = __float2bfloat16_rn(v.x - __bfloat162float(h0));
    __nv_bfloat16 l1 = __float2bfloat16_rn(v.y - __bfloat162float(h1));
    __nv_bfloat162 H = {h0, h1}, L = {l0, l1};
    __nv_bfloat162* d0 = (__nv_bfloat162*)(dst + c);
    d0[0] = H;
    if (mode == 0) { d0[256] = L; d0[512] = H; }
    else           { d0[256] = H; d0[512] = L; }
}

// ---------------------------------------------------------------------------
// Bitmap build: 4M index entries -> atomicOr bits. Entries 4g..4g+3 share one
// (h, n) row (128 entries/row, 4-aligned). Must run after the zero pass.
// ---------------------------------------------------------------------------
__global__ void __launch_bounds__(256)
bm_build(const int* __restrict__ sidx)
{
    const int gid = blockIdx.x * 256 + threadIdx.x;      // 1M threads
    int4 v = ((const int4*)sidx)[gid];
    uint32_t* rowp = g_bm + ((size_t)(gid >> 5) << 7);   // (entry>>7)*128
    atomicOr(rowp + ((uint32_t)v.x >> 5), 1u << (v.x & 31));
    atomicOr(rowp + ((uint32_t)v.y >> 5), 1u << (v.y & 31));
    atomicOr(rowp + ((uint32_t)v.z >> 5), 1u << (v.z & 31));
    atomicOr(rowp + ((uint32_t)v.w >> 5), 1u << (v.w & 31));
}

// ---------------------------------------------------------------------------
// HMMA projection GEMM (unchanged structure; Q now stored fp16).
// 3-stage cp.async pipeline, CTA 128x128, 8 warps 4(M)x2(N), warp tile 32x64.
// ---------------------------------------------------------------------------
#define BKG    32
#define NITER  (K_TOT / BKG)     // 48
#define APAD   40                // 80B row stride, ldsm conflict-free
#define AST_B  (128 * APAD * 2)  // 10240B per operand per stage
#define STAGE  (2 * AST_B)       // 20480B
#define SMEMSZ (3 * STAGE)       // 61440B

__global__ void __launch_bounds__(256, 2)
proj_mma_kernel(const float* __restrict__ bq, const float* __restrict__ bk)
{
    extern __shared__ __align__(16) char smem[];
    const uint32_t sbase = smem_u32_of(smem);

    const int t      = threadIdx.x;
    const int wid    = t >> 5;
    const int lane   = t & 31;
    const int warp_m = wid & 3;
    const int warp_n = wid >> 2;
    const int z      = blockIdx.z;
    const int rowBase = blockIdx.y * 128;
    const int colBase = blockIdx.x * 128;

    const __nv_bfloat16* Asrc = g_X2 + (size_t)rowBase * K_TOT;
    const __nv_bfloat16* Bsrc = (z ? g_W2k : g_W2q) + (size_t)colBase * K_TOT;

    const int cr = t >> 2, cc = t & 3;
    const __nv_bfloat16* gA0 = Asrc + (size_t)cr * K_TOT + cc * 8;
    const __nv_bfloat16* gA1 = Asrc + (size_t)(cr + 64) * K_TOT + cc * 8;
    const __nv_bfloat16* gB0 = Bsrc + (size_t)cr * K_TOT + cc * 8;
    const __nv_bfloat16* gB1 = Bsrc + (size_t)(cr + 64) * K_TOT + cc * 8;

    uint32_t sA0[3], sA1[3], sB0[3], sB1[3], aAd[3], bAd[3];
    {
        const int arow = warp_m * 32 + (lane & 15);
        const int kcol = (lane >> 4) * 8;
        const int brow = warp_n * 64 + (lane & 15);
        #pragma unroll
        for (int s = 0; s < 3; s++) {
            const uint32_t a0 = sbase + s * STAGE;
            const uint32_t b0 = a0 + AST_B;
            sA0[s] = a0 + (cr * APAD + cc * 8) * 2;
            sA1[s] = a0 + ((cr + 64) * APAD + cc * 8) * 2;
            sB0[s] = b0 + (cr * APAD + cc * 8) * 2;
            sB1[s] = b0 + ((cr + 64) * APAD + cc * 8) * 2;
            aAd[s] = a0 + (arow * APAD + kcol) * 2;
            bAd[s] = b0 + (brow * APAD + kcol) * 2;
        }
    }

    float acc[2][8][4];
    #pragma unroll
    for (int mi = 0; mi < 2; mi++)
        #pragma unroll
        for (int ni = 0; ni < 8; ni++)
            #pragma unroll
            for (int e = 0; e < 4; e++) acc[mi][ni][e] = 0.0f;

    #pragma unroll
    for (int s = 0; s < 2; s++) {
        const int k0 = s * BKG;
        cp16(sA0[s], gA0 + k0); cp16(sA1[s], gA1 + k0);
        cp16(sB0[s], gB0 + k0); cp16(sB1[s], gB1 + k0);
        CP_COMMIT();
    }

    #pragma unroll 1
    for (int it = 0; it < NITER; ++it) {
        const int b = it % 3;
        if (it + 1 < NITER) CP_WAIT1(); else CP_WAIT0();
        __syncthreads();

        if (it + 2 < NITER) {
            const int k2 = (it + 2) * BKG;
            const int nb = (it + 2) % 3;
            cp16(sA0[nb], gA0 + k2); cp16(sA1[nb], gA1 + k2);
            cp16(sB0[nb], gB0 + k2); cp16(sB1[nb], gB1 + k2);
            CP_COMMIT();
        }

        #pragma unroll
        for (int ks = 0; ks < 2; ks++) {
            uint32_t a[2][4];
            ldsm_x4(a[0], aAd[b] + ks * 32);
            ldsm_x4(a[1], aAd[b] + 16 * (APAD * 2) + ks * 32);
            uint32_t bf[8][2];
            #pragma unroll
            for (int nb4 = 0; nb4 < 4; nb4++) {
                uint32_t r[4];
                ldsm_x4(r, bAd[b] + nb4 * 16 * (APAD * 2) + ks * 32);
                bf[2 * nb4 + 0][0] = r[0]; bf[2 * nb4 + 0][1] = r[2];
                bf[2 * nb4 + 1][0] = r[1]; bf[2 * nb4 + 1][1] = r[3];
            }
            #pragma unroll
            for (int mi = 0; mi < 2; mi++)
                #pragma unroll
                for (int ni = 0; ni < 8; ni++)
                    mma_bf16(acc[mi][ni], a[mi], bf[ni]);
        }
    }

    // Epilogue: fp16 stores for both Q and K.
    const float* bias = z ? bk : bq;
    __half* dstb = z ? g_Kh : g_Qh;
    const int mrow = rowBase + warp_m * 32 + (lane >> 2);
    #pragma unroll
    for (int mi = 0; mi < 2; mi++) {
        #pragma unroll
        for (int ni = 0; ni < 8; ni++) {
            const int gn = colBase + warp_n * 64 + ni * 8 + (lane & 3) * 2;
            const float2 bb = *(const float2*)(bias + gn);
            const int gm0 = mrow + mi * 16;
            __half2 o0 = __floats2half2_rn(acc[mi][ni][0] + bb.x, acc[mi][ni][1] + bb.y);
            __half2 o1 = __floats2half2_rn(acc[mi][ni][2] + bb.x, acc[mi][ni][3] + bb.y);
            *(__half2*)(dstb + (size_t)gm0 * EMB + gn)       = o0;
            *(__half2*)(dstb + (size_t)(gm0 + 8) * EMB + gn) = o1;
        }
    }
}

// ---------------------------------------------------------------------------
// Masked dense score kernel (replaces gather+scatter).
// One CTA per output tile [h, n0:n0+128, c0:c0+128]:
//   S = Q_h[n0:,:] @ K_h[c0:,:]^T via fp16 mma (same proven fragment layout as
//   proj GEMM: both operands row-major [rows,64], non-trans ldsm, mma.row.col),
//   stage S in smem, apply bitmap mask + 1/sqrt(64) scale, stream out float4.
// Duplicate sparse indices give the same dot product -> matches scatter.
// ---------------------------------------------------------------------------
#define MPAD    72                      // halves per input row (64+8) -> 144B
#define MS_QS   0
#define MS_KS   (128 * MPAD * 2)        // 18432
#define SROW    132                     // floats per staged row
#define MS_BM   (128 * SROW * 4)        // 67584 (stage overlays Qs/Ks only)
#define MS_SMEM (MS_BM + 128 * 4 * 4)   // + 2KB bitmap tile = 69632

__global__ void __launch_bounds__(256, 2)
masked_scores_kernel(float* __restrict__ out)
{
    extern __shared__ __align__(16) char smem[];
    const uint32_t sb = smem_u32_of(smem);
    const int t = threadIdx.x, wid = t >> 5, lane = t & 31;
    const int bid = blockIdx.x;
    const int h  = bid >> 10;
    const int n0 = ((bid >> 5) & 31) * 128;
    const int c0 = (bid & 31) * 128;

    // Load Q and K tiles [128 x 64] fp16, rows padded to 72 halves.
    const __half* Qsrc = g_Qh + (size_t)n0 * EMB + h * HD;
    const __half* Ksrc = g_Kh + (size_t)c0 * EMB + h * HD;
    #pragma unroll
    for (int i = 0; i < 4; i++) {
        const int c = t + i * 256;           // 1024 uint4 chunks per tile
        const int r = c >> 3, cc = c & 7;
        *(uint4*)(smem + MS_QS + (r * MPAD + cc * 8) * 2) =
            *(const uint4*)(Qsrc + (size_t)r * EMB + cc * 8);
        *(uint4*)(smem + MS_KS + (r * MPAD + cc * 8) * 2) =
            *(const uint4*)(Ksrc + (size_t)r * EMB + cc * 8);
    }
    // Bitmap tile: 128 rows x 4 words.
    {
        const int w = t * 2;                 // 512 words, 2 per thread
        const int r = w >> 2, wi = w & 3;
        const uint32_t* src = g_bm + ((((size_t)h << 12) | (n0 + r)) << 7) + (c0 >> 5) + wi;
        *(uint2*)(smem + MS_BM + w * 4) = *(const uint2*)src;
    }
    __syncthreads();

    const int warp_m = wid & 3;              // 32 rows each
    const int warp_n = wid >> 2;             // 64 cols each
    float acc[2][8][4];
    #pragma unroll
    for (int mi = 0; mi < 2; mi++)
        #pragma unroll
        for (int ni = 0; ni < 8; ni++)
            #pragma unroll
            for (int e = 0; e < 4; e++) acc[mi][ni][e] = 0.0f;

    const uint32_t aBase = sb + MS_QS + ((warp_m * 32 + (lane & 15)) * MPAD + (lane >> 4) * 8) * 2;
    const uint32_t bBase = sb + MS_KS + ((warp_n * 64 + (lane & 15)) * MPAD + (lane >> 4) * 8) * 2;
    #pragma unroll
    for (int ks = 0; ks < 4; ks++) {         // K = 64 = 4 x k16
        uint32_t a[2][4];
        ldsm_x4(a[0], aBase + ks * 32);
        ldsm_x4(a[1], aBase + 16 * (MPAD * 2) + ks * 32);
        uint32_t bf[8][2];
        #pragma unroll
        for (int nb = 0; nb < 4; nb++) {
            uint32_t r[4];
            ldsm_x4(r, bBase + nb * 16 * (MPAD * 2) + ks * 32);
            bf[2 * nb + 0][0] = r[0]; bf[2 * nb + 0][1] = r[2];
            bf[2 * nb + 1][0] = r[1]; bf[2 * nb + 1][1] = r[3];
        }
        #pragma unroll
        for (int mi = 0; mi < 2; mi++)
            #pragma unroll
            for (int ni = 0; ni < 8; ni++)
                mma_f16(acc[mi][ni], a[mi], bf[ni]);
    }
    __syncthreads();        // inputs dead; stage buffer overlays them

    // Stage raw scores: frag (row lane>>2 (+8), cols (lane&3)*2) -> smem rows.
    const int R0 = warp_m * 32 + (lane >> 2);
    const int C0 = warp_n * 64 + (lane & 3) * 2;
    #pragma unroll
    for (int mi = 0; mi < 2; mi++) {
        #pragma unroll
        for (int ni = 0; ni < 8; ni++) {
            const int R = R0 + mi * 16, C = C0 + ni * 8;
            float2 lo = { acc[mi][ni][0], acc[mi][ni][1] };
            float2 hi = { acc[mi][ni][2], acc[mi][ni][3] };
            *(float2*)(smem + ((size_t)R * SROW + C) * 4)       = lo;
            *(float2*)(smem + ((size_t)(R + 8) * SROW + C) * 4) = hi;
        }
    }
    __syncthreads();

    // Masked, scaled, coalesced writeout: warp = row, lane = float4 column.
    const uint32_t* bmS = (const uint32_t*)(smem + MS_BM);
    #pragma unroll 1
    for (int p = 0; p < 16; p++) {
        const int row = p * 8 + wid;
        float4 s = *(const float4*)(smem + ((size_t)row * SROW + lane * 4) * 4);
        const uint32_t word = bmS[row * 4 + (lane >> 3)];
        const uint32_t sh = (lane & 7) * 4;
        float4 o;
        o.x = ((word >> (sh + 0)) & 1u) ? s.x * 0.125f : 0.0f;
        o.y = ((word >> (sh + 1)) & 1u) ? s.y * 0.125f : 0.0f;
        o.z = ((word >> (sh + 2)) & 1u) ? s.z * 0.125f : 0.0f;
        o.w = ((word >> (sh + 3)) & 1u) ? s.w * 0.125f : 0.0f;
        *(float4*)(out + (((size_t)((h << 12) | (n0 + row))) << 12) + c0 + lane * 4) = o;
    }
}

// ---------------------------------------------------------------------------
extern "C" void kernel_launch(void* const* d_in, const int* in_sizes, int n_in,
                              void* d_out, int out_size)
{
    const float* emb = (const float*)d_in[0];
    const float* Wq  = (const float*)d_in[1];
    const float* bq  = (const float*)d_in[2];
    const float* Wk  = (const float*)d_in[3];
    const float* bk  = (const float*)d_in[4];
    const int*   idx = (const int*)d_in[5];
    float* out = (float*)d_out;

    static int attrs_set = 0;
    if (!attrs_set) {
        cudaFuncSetAttribute(proj_mma_kernel,
                             cudaFuncAttributeMaxDynamicSharedMemorySize, SMEMSZ);
        cudaFuncSetAttribute(masked_scores_kernel,
                             cudaFuncAttributeMaxDynamicSharedMemorySize, MS_SMEM);
        attrs_set = 1;
    }

    split_convert_all<<<CONV_BLKS + BMZ_BLKS, 256>>>(emb, Wq, Wk);
    bm_build<<<(N_HEADS * N_NODES * KSP) / (4 * 256), 256>>>(idx);

    dim3 ggrid(EMB / 128, N_NODES / 128, 2);   // 4 x 32 x 2
    proj_mma_kernel<<<ggrid, 256, SMEMSZ>>>(bq, bk);

    masked_scores_kernel<<<N_HEADS * 32 * 32, 256, MS_SMEM>>>(out);
}